// round 5
// baseline (speedup 1.0000x reference)
#include <cuda_runtime.h>
#include <math.h>

#define BB   4
#define CC   64
#define HH   192
#define WW   192
#define HWX  (HH*WW)
#define OFFC 18
#define HID  4

typedef unsigned long long u64;

// packed fp32x2 FMA: d = a*b + d (lane-wise, exact IEEE fp32)
#define FMA2(d, a, b) asm("fma.rn.f32x2 %0, %1, %2, %0;" : "+l"(d) : "l"(a), "l"(b))
#define UNPK(lo, hi, v) asm("mov.b64 {%0,%1}, %2;" : "=f"(lo), "=f"(hi) : "l"(v))

// scratch (device globals; allocations are forbidden)
__device__ float g_off[BB*OFFC*HH*WW];        // 10.6 MB
__device__ float g_h  [BB*CC*HH*WW];          // 37.7 MB
__device__ float g_pool[BB*CC];               // post-BN channel sums
__device__ float g_cw  [BB*CC];
__device__ float g_dwT  [9*CC*CC];            // [kk][o][c]
__device__ float2 g_offw2[(CC/2)*9*OFFC];     // [(c2*9+t)*18+o] = (w[2c2],w[2c2+1])

// dynamic smem layout for deform kernel (in floats)
#define DW_S_OFF    0                          // 4096
#define SAMP_S_OFF  (DW_S_OFF + CC*CC)         // 32 c2-rows * 260 = 8320
#define SAMP_PITCH  260
#define MWY_OFF     (SAMP_S_OFF + 32*SAMP_PITCH)
#define MWX_OFF     (MWY_OFF + 9*128)
#define MY0_OFF     (MWX_OFF + 9*128)
#define MX0_OFF     (MY0_OFF + 9*128)
#define DEFORM_SMEM_FLOATS (MX0_OFF + 9*128)
#define DEFORM_SMEM_BYTES  (DEFORM_SMEM_FLOATS * 4)   // 68096

// ---------------------------------------------------------------------------
// K0: weight transposes + zero pool accumulators (once per launch; tiny)
// ---------------------------------------------------------------------------
__global__ __launch_bounds__(256) void transpose_w_kernel(
        const float* __restrict__ dw, const float* __restrict__ off_w) {
    int d = blockIdx.x*256 + threadIdx.x;
    if (blockIdx.x == 0) g_pool[threadIdx.x] = 0.f;
    if (d < 9*CC*CC) {
        int kk = d >> 12;
        int o  = (d >> 6) & 63;
        int c  = d & 63;
        g_dwT[d] = dw[(o*CC + c)*9 + kk];
    } else {
        int e = d - 9*CC*CC;
        if (e < (CC/2)*9*OFFC) {
            int o  = e % OFFC;
            int k  = e / OFFC;      // c2*9 + t
            int c2 = k / 9, t = k % 9;
            float2 w;
            w.x = off_w[(o*CC + 2*c2    )*9 + t];
            w.y = off_w[(o*CC + 2*c2 + 1)*9 + t];
            g_offw2[e] = w;
        }
    }
}

// ---------------------------------------------------------------------------
// K1: 3x3 conv 64 -> 18 (offset prediction), pad 1.  f32x2 channel-paired.
// tile 64x8, 256 threads, 2 pixels/thread (x and x+32); grid (3, 24, 4)
// ---------------------------------------------------------------------------
__global__ __launch_bounds__(256) void offset_conv_kernel(
        const float* __restrict__ x,
        const float* __restrict__ off_b) {
    __shared__ __align__(16) float2 wsm2[(CC/2)*9*OFFC];  // 41.5 KB
    __shared__ __align__(16) float  xs2[660*2];           // 2 planes interleaved

    const int tid = threadIdx.x;
    const int bx = blockIdx.x, by = blockIdx.y, b = blockIdx.z;
    const int lx = tid & 31, ly = tid >> 5;
    const int xg0 = bx*64 + lx;
    const int yg = by*8 + ly;

    for (int t = tid; t < (CC/2)*9*OFFC/2; t += 256)
        ((float4*)wsm2)[t] = ((const float4*)g_offw2)[t];

    u64 acc2[OFFC][2];
    #pragma unroll
    for (int o = 0; o < OFFC; ++o) { acc2[o][0] = 0ull; acc2[o][1] = 0ull; }

    const float* xb = x + (size_t)b*CC*HWX;

    #pragma unroll 1
    for (int c2 = 0; c2 < 32; ++c2) {
        __syncthreads();
        // stage two channel planes, interleaved by parity
        #pragma unroll 2
        for (int par = 0; par < 2; ++par) {
            const float* xp = xb + (2*c2 + par)*HWX;
            for (int t = tid; t < 660; t += 256) {
                int r = t / 66, q = t % 66;
                int gy = by*8 + r - 1, gx = bx*64 + q - 1;
                float v = 0.f;
                if (gy >= 0 && gy < HH && gx >= 0 && gx < WW)
                    v = xp[gy*WW + gx];
                xs2[2*t + par] = v;
            }
        }
        __syncthreads();
        #pragma unroll
        for (int t = 0; t < 9; ++t) {
            int i = t/3, j = t%3;
            int pos0 = (ly+i)*66 + lx + j;
            u64 xv0 = *(const u64*)&xs2[pos0*2];
            u64 xv1 = *(const u64*)&xs2[(pos0+32)*2];
            const ulonglong2* w = (const ulonglong2*)&wsm2[(c2*9 + t)*OFFC];
            #pragma unroll
            for (int o2 = 0; o2 < 9; ++o2) {
                ulonglong2 ww = w[o2];
                FMA2(acc2[2*o2  ][0], ww.x, xv0);
                FMA2(acc2[2*o2  ][1], ww.x, xv1);
                FMA2(acc2[2*o2+1][0], ww.y, xv0);
                FMA2(acc2[2*o2+1][1], ww.y, xv1);
            }
        }
    }
    #pragma unroll
    for (int o = 0; o < OFFC; ++o) {
        float l0, h0, l1, h1;
        UNPK(l0, h0, acc2[o][0]);
        UNPK(l1, h1, acc2[o][1]);
        float bv = off_b[o];
        g_off[((b*OFFC + o)*HH + yg)*WW + xg0     ] = l0 + h0 + bv;
        g_off[((b*OFFC + o)*HH + yg)*WW + xg0 + 32] = l1 + h1 + bv;
    }
}

// ---------------------------------------------------------------------------
// K2: deformable 3x3 conv 64->64 + BN + fused pool sums.  f32x2 GEMM.
// block = 2 rows x 64 px = 128 pixels, all 64 out ch; 256 threads,
// 4 adjacent pixels x 8 outputs per thread; grid (3, 96, 4); dynamic smem
// ---------------------------------------------------------------------------
__global__ __launch_bounds__(256) void deform_bn_kernel(
        const float* __restrict__ x,
        const float* __restrict__ db,
        const float* __restrict__ gma,
        const float* __restrict__ bta,
        const float* __restrict__ mean,
        const float* __restrict__ var) {
    extern __shared__ __align__(16) float smem[];
    float* dw_s   = smem + DW_S_OFF;     // one tap [o][c]: 16 KB
    float* samp_s = smem + SAMP_S_OFF;   // [c2][px][parity], pitch 260
    float* m_wy   = smem + MWY_OFF;
    float* m_wx   = smem + MWX_OFF;
    int*   m_y0   = (int*)(smem + MY0_OFF);
    int*   m_x0   = (int*)(smem + MX0_OFF);

    const int tid = threadIdx.x;
    const int b   = blockIdx.z;
    const int y0  = blockIdx.y * 2;
    const int x0b = blockIdx.x * 64;
    const int pq  = tid & 31;        // pixel-quad index: pixels 4pq..4pq+3
    const int og  = tid >> 5;        // output-channel group 0..7
    const int ppg = tid & 127;       // gather pixel 0..127
    const int cg  = tid >> 7;        // gather channel parity 0..1

    const float* xb   = x     + (size_t)b*CC*HWX;
    const float* offb = g_off + (size_t)b*OFFC*HWX;

    // bilinear metadata for all 9 taps x 128 pixels
    for (int t = tid; t < 9*128; t += 256) {
        int kk = t >> 7, p = t & 127;
        int row = p >> 6, col = p & 63;
        int yy = y0 + row, xx = x0b + col;
        int i = kk/3, j = kk%3;
        float oy = offb[(2*kk  )*HWX + yy*WW + xx];
        float ox = offb[(2*kk+1)*HWX + yy*WW + xx];
        float py = (float)(yy + i - 1) + oy;
        float px = (float)(xx + j - 1) + ox;
        float fy = floorf(py), fx = floorf(px);
        m_y0[t] = (int)fy;  m_x0[t] = (int)fx;
        m_wy[t] = py - fy;  m_wx[t] = px - fx;
    }

    u64 acc2[8][4];
    #pragma unroll
    for (int r = 0; r < 8; ++r)
        #pragma unroll
        for (int p = 0; p < 4; ++p) acc2[r][p] = 0ull;

    __syncthreads();

    #pragma unroll 1
    for (int kk = 0; kk < 9; ++kk) {
        // ---- gather 64x128 samples (32 per thread, fixed pixel) ----
        {
            int mi = kk*128 + ppg;
            int yq = m_y0[mi], xq = m_x0[mi];
            float wy = m_wy[mi], wx = m_wx[mi];
            float vy0 = ((unsigned)yq     < (unsigned)HH) ? 1.f : 0.f;
            float vy1 = ((unsigned)(yq+1) < (unsigned)HH) ? 1.f : 0.f;
            float vx0 = ((unsigned)xq     < (unsigned)WW) ? 1.f : 0.f;
            float vx1 = ((unsigned)(xq+1) < (unsigned)WW) ? 1.f : 0.f;
            float w00 = (1.f-wy)*(1.f-wx)*vy0*vx0;
            float w01 = (1.f-wy)*wx      *vy0*vx1;
            float w10 = wy*(1.f-wx)      *vy1*vx0;
            float w11 = wy*wx            *vy1*vx1;
            int yc0 = min(max(yq,   0), HH-1);
            int yc1 = min(max(yq+1, 0), HH-1);
            int xc0 = min(max(xq,   0), WW-1);
            int xc1 = min(max(xq+1, 0), WW-1);
            int o00 = yc0*WW + xc0, o01 = yc0*WW + xc1;
            int o10 = yc1*WW + xc0, o11 = yc1*WW + xc1;
            const float* xc = xb + cg*HWX;
            float* sp = samp_s + 2*ppg + cg;
            #pragma unroll
            for (int r = 0; r < 32; ++r) {
                float v = w00*xc[o00] + w01*xc[o01] + w10*xc[o10] + w11*xc[o11];
                sp[r*SAMP_PITCH] = v;      // channel c = 2r+cg -> row r, parity cg
                xc += 2*HWX;
            }
        }
        // ---- stage this tap's weights (coalesced, pre-transposed, [o][c]) ----
        for (int t = tid; t < 1024; t += 256)
            ((float4*)dw_s)[t] = ((const float4*)g_dwT)[kk*1024 + t];
        __syncthreads();

        // ---- f32x2 GEMM: acc2[r][p] += (w_even,w_odd)*(s_even,s_odd) ----
        const ulonglong2* dwv = (const ulonglong2*)dw_s;
        #pragma unroll 4
        for (int c4 = 0; c4 < 16; ++c4) {
            const ulonglong2* sa = (const ulonglong2*)&samp_s[(2*c4  )*SAMP_PITCH + 8*pq];
            const ulonglong2* sb = (const ulonglong2*)&samp_s[(2*c4+1)*SAMP_PITCH + 8*pq];
            ulonglong2 sa01 = sa[0], sa23 = sa[1];
            ulonglong2 sb01 = sb[0], sb23 = sb[1];
            #pragma unroll
            for (int r = 0; r < 8; ++r) {
                ulonglong2 w = dwv[(og*8 + r)*16 + c4];  // (pair a, pair b)
                FMA2(acc2[r][0], w.x, sa01.x);
                FMA2(acc2[r][1], w.x, sa01.y);
                FMA2(acc2[r][2], w.x, sa23.x);
                FMA2(acc2[r][3], w.x, sa23.y);
                FMA2(acc2[r][0], w.y, sb01.x);
                FMA2(acc2[r][1], w.y, sb01.y);
                FMA2(acc2[r][2], w.y, sb23.x);
                FMA2(acc2[r][3], w.y, sb23.y);
            }
        }
        __syncthreads();
    }

    // epilogue: combine halves, bias, BN, store, fused pool partial sums
    const int p0 = 4*pq;
    const int row = p0 >> 6, col = p0 & 63;
    #pragma unroll
    for (int r = 0; r < 8; ++r) {
        int o = og*8 + r;
        float inv = rsqrtf(var[o] + 1e-5f);
        float sc = gma[o]*inv, mu = mean[o], bt = bta[o], bv = db[o];
        float4 v; float lo, hi;
        UNPK(lo, hi, acc2[r][0]); v.x = (lo + hi + bv - mu)*sc + bt;
        UNPK(lo, hi, acc2[r][1]); v.y = (lo + hi + bv - mu)*sc + bt;
        UNPK(lo, hi, acc2[r][2]); v.z = (lo + hi + bv - mu)*sc + bt;
        UNPK(lo, hi, acc2[r][3]); v.w = (lo + hi + bv - mu)*sc + bt;
        *(float4*)&g_h[((b*CC + o)*HH + y0 + row)*WW + x0b + col] = v;
        float s = (v.x + v.y) + (v.z + v.w);
        #pragma unroll
        for (int off = 16; off > 0; off >>= 1)
            s += __shfl_xor_sync(0xffffffffu, s, off);
        if (pq == 0) atomicAdd(&g_pool[b*CC + o], s);
    }
}

// ---------------------------------------------------------------------------
// K3: SE MLP (hid=4): one block (scales pooled sums by 1/HW)
// ---------------------------------------------------------------------------
__global__ __launch_bounds__(256) void ca_kernel(
        const float* __restrict__ w1, const float* __restrict__ b1,
        const float* __restrict__ w2, const float* __restrict__ b2) {
    __shared__ float t[BB*HID];
    const int tid = threadIdx.x;
    const int b = tid >> 6, c = tid & 63;
    if (c < HID) {
        float s = b1[c];
        for (int cc = 0; cc < CC; ++cc)
            s += w1[c*CC + cc] * (g_pool[b*CC + cc] * (1.f/(float)HWX));
        t[b*HID + c] = fmaxf(s, 0.f);
    }
    __syncthreads();
    float s = b2[c];
    #pragma unroll
    for (int h = 0; h < HID; ++h) s += w2[c*HID + h] * t[b*HID + h];
    g_cw[tid] = 1.f / (1.f + expf(-s));
}

// ---------------------------------------------------------------------------
// K4: spatial attention 7x7 conv -> sigmoid -> fused final output
// f32x2 channel-paired. tile 64x8, 256 threads; grid (3, 24, 4)
// ---------------------------------------------------------------------------
__global__ __launch_bounds__(256) void sa_final_kernel(
        const float* __restrict__ sa_w, const float* __restrict__ sa_b,
        float* __restrict__ out) {
    __shared__ __align__(16) float2 ws2[49*32];   // [tap][c2]
    __shared__ __align__(16) float  xs2[980*2];   // 2 planes interleaved
    __shared__ __align__(16) float2 cw2[32];
    __shared__ float cws[CC];
    const int tid = threadIdx.x;
    const int bx = blockIdx.x, by = blockIdx.y, b = blockIdx.z;
    const int lx = tid & 31, ly = tid >> 5;
    const int xg0 = bx*64 + lx, yg = by*8 + ly;

    for (int e = tid; e < 49*32; e += 256) {
        int t = e >> 5, c2 = e & 31;
        float2 w;
        w.x = sa_w[(2*c2  )*49 + t];
        w.y = sa_w[(2*c2+1)*49 + t];
        ws2[e] = w;
    }
    if (tid < CC) cws[tid] = g_cw[b*CC + tid];
    if (tid < 32) {
        float2 c;
        c.x = g_cw[b*CC + 2*tid];
        c.y = g_cw[b*CC + 2*tid + 1];
        cw2[tid] = c;
    }

    u64 acc2_0 = 0ull, acc2_1 = 0ull;
    const float* hb = g_h + (size_t)b*CC*HWX;

    #pragma unroll 1
    for (int c2 = 0; c2 < 32; ++c2) {
        __syncthreads();
        #pragma unroll 2
        for (int par = 0; par < 2; ++par) {
            const float* hp = hb + (2*c2 + par)*HWX;
            for (int t = tid; t < 980; t += 256) {
                int r = t / 70, q = t % 70;
                int gy = by*8 + r - 3, gx = bx*64 + q - 3;
                float v = 0.f;
                if (gy >= 0 && gy < HH && gx >= 0 && gx < WW)
                    v = hp[gy*WW + gx];
                xs2[2*t + par] = v;
            }
        }
        __syncthreads();
        u64 t0 = 0ull, t1 = 0ull;
        #pragma unroll
        for (int dy = 0; dy < 7; ++dy) {
            int base = ((ly+dy)*70 + lx)*2;
            #pragma unroll
            for (int dx = 0; dx < 7; ++dx) {
                u64 w = *(const u64*)&ws2[(dy*7+dx)*32 + c2];
                u64 xv0 = *(const u64*)&xs2[base + 2*dx];
                u64 xv1 = *(const u64*)&xs2[base + 64 + 2*dx];
                FMA2(t0, w, xv0);
                FMA2(t1, w, xv1);
            }
        }
        u64 cwp = *(const u64*)&cw2[c2];
        FMA2(acc2_0, cwp, t0);
        FMA2(acc2_1, cwp, t1);
    }
    float l, h;
    UNPK(l, h, acc2_0); float acc0 = sa_b[0] + l + h;
    UNPK(l, h, acc2_1); float acc1 = sa_b[0] + l + h;
    float sw0 = 1.f / (1.f + expf(-acc0));
    float sw1 = 1.f / (1.f + expf(-acc1));

    // fused finalize: out = h * cw * sw for all 64 channels of this tile
    const int base = yg*WW + xg0;
    #pragma unroll 4
    for (int c = 0; c < CC; ++c) {
        float cw = cws[c];
        float h0 = hb[c*HWX + base];
        float h1 = hb[c*HWX + base + 32];
        out[((size_t)(b*CC + c))*HWX + base     ] = h0*cw*sw0;
        out[((size_t)(b*CC + c))*HWX + base + 32] = h1*cw*sw1;
    }
}

// ---------------------------------------------------------------------------
extern "C" void kernel_launch(void* const* d_in, const int* in_sizes, int n_in,
                              void* d_out, int out_size) {
    const float* x      = (const float*)d_in[0];
    const float* off_w  = (const float*)d_in[1];
    const float* off_b  = (const float*)d_in[2];
    const float* dw     = (const float*)d_in[3];
    const float* db     = (const float*)d_in[4];
    const float* bn_g   = (const float*)d_in[5];
    const float* bn_b   = (const float*)d_in[6];
    const float* bn_m   = (const float*)d_in[7];
    const float* bn_v   = (const float*)d_in[8];
    const float* ca_w1  = (const float*)d_in[9];
    const float* ca_b1  = (const float*)d_in[10];
    const float* ca_w2  = (const float*)d_in[11];
    const float* ca_b2  = (const float*)d_in[12];
    const float* sa_w   = (const float*)d_in[13];
    const float* sa_b   = (const float*)d_in[14];
    float* out = (float*)d_out;

    cudaFuncSetAttribute(deform_bn_kernel,
                         cudaFuncAttributeMaxDynamicSharedMemorySize,
                         DEFORM_SMEM_BYTES);

    transpose_w_kernel<<<(9*CC*CC + (CC/2)*9*OFFC + 255)/256, 256>>>(dw, off_w);
    offset_conv_kernel<<<dim3(WW/64, HH/8, BB), 256>>>(x, off_b);
    deform_bn_kernel  <<<dim3(WW/64, HH/2, BB), 256, DEFORM_SMEM_BYTES>>>(
                          x, db, bn_g, bn_b, bn_m, bn_v);
    ca_kernel         <<<1, 256>>>(ca_w1, ca_b1, ca_w2, ca_b2);
    sa_final_kernel   <<<dim3(WW/64, HH/8, BB), 256>>>(sa_w, sa_b, out);
}

// round 6
// speedup vs baseline: 1.0705x; 1.0705x over previous
#include <cuda_runtime.h>
#include <math.h>

#define BB   4
#define CC   64
#define HH   192
#define WW   192
#define HWX  (HH*WW)
#define OFFC 18
#define HID  4

// scratch (device globals; allocations are forbidden)
__device__ float g_off[BB*OFFC*HH*WW];        // 10.6 MB
__device__ float g_h  [BB*CC*HH*WW];          // 37.7 MB
__device__ float g_pool[BB*CC];               // post-BN channel sums
__device__ float g_cw  [BB*CC];
__device__ float g_dwT  [9*CC*CC];            // [kk][o][c]
__device__ float g_offwT[CC*9*OFFC];          // [(c*9+t)*18 + o]

// dynamic smem layout for deform kernel (in floats)
#define DW_S_OFF    0                          // 4096 floats (one tap [o][c])
#define SAMP_S_OFF  (DW_S_OFF + CC*CC)         // 8448 floats (64*132)
#define DEFORM_SMEM_FLOATS (SAMP_S_OFF + CC*132)
#define DEFORM_SMEM_BYTES  (DEFORM_SMEM_FLOATS * 4)   // 50176 B -> 4 CTAs/SM

// ---------------------------------------------------------------------------
// K0: weight transposes + zero pool accumulators (once per launch; tiny)
// ---------------------------------------------------------------------------
__global__ __launch_bounds__(256) void transpose_w_kernel(
        const float* __restrict__ dw, const float* __restrict__ off_w) {
    int d = blockIdx.x*256 + threadIdx.x;
    if (blockIdx.x == 0) g_pool[threadIdx.x] = 0.f;
    if (d < 9*CC*CC) {
        int kk = d >> 12;
        int o  = (d >> 6) & 63;
        int c  = d & 63;
        g_dwT[d] = dw[(o*CC + c)*9 + kk];
    } else {
        int e = d - 9*CC*CC;
        if (e < CC*9*OFFC) {
            int k = e / OFFC;      // c*9+t
            int o = e % OFFC;
            int c = k / 9, t = k % 9;
            g_offwT[e] = off_w[(o*CC + c)*9 + t];
        }
    }
}

// ---------------------------------------------------------------------------
// K1: 3x3 conv 64 -> 18 (offset prediction), pad 1
// tile 64x8, 256 threads, 2 pixels/thread (x and x+32); grid (3, 24, 4)
// ---------------------------------------------------------------------------
__global__ __launch_bounds__(256) void offset_conv_kernel(
        const float* __restrict__ x,
        const float* __restrict__ off_b) {
    __shared__ float wsm[CC*9*OFFC];   // [(c*9+t)*18+o]  41.5 KB
    __shared__ float xs[10*66];

    const int tid = threadIdx.x;
    const int bx = blockIdx.x, by = blockIdx.y, b = blockIdx.z;
    const int lx = tid & 31, ly = tid >> 5;
    const int xg0 = bx*64 + lx;
    const int yg = by*8 + ly;

    for (int t = tid; t < CC*9*OFFC/4; t += 256)
        ((float4*)wsm)[t] = ((const float4*)g_offwT)[t];

    float acc[OFFC][2];
    #pragma unroll
    for (int o = 0; o < OFFC; ++o) { float bv = off_b[o]; acc[o][0] = bv; acc[o][1] = bv; }

    const float* xb = x + (size_t)b*CC*HWX;

    #pragma unroll 1
    for (int c = 0; c < CC; ++c) {
        __syncthreads();
        for (int t = tid; t < 660; t += 256) {
            int r = t / 66, q = t % 66;
            int gy = by*8 + r - 1, gx = bx*64 + q - 1;
            float v = 0.f;
            if (gy >= 0 && gy < HH && gx >= 0 && gx < WW)
                v = xb[c*HWX + gy*WW + gx];
            xs[t] = v;
        }
        __syncthreads();
        const float* wc = wsm + c*9*OFFC;
        #pragma unroll
        for (int t = 0; t < 9; ++t) {
            int i = t/3, j = t%3;
            float xa  = xs[(ly+i)*66 + lx + j];
            float xc2 = xs[(ly+i)*66 + lx + 32 + j];
            const float2* w2 = (const float2*)(wc + t*OFFC);
            #pragma unroll
            for (int o2 = 0; o2 < 9; ++o2) {
                float2 w = w2[o2];
                acc[2*o2  ][0] += w.x*xa; acc[2*o2  ][1] += w.x*xc2;
                acc[2*o2+1][0] += w.y*xa; acc[2*o2+1][1] += w.y*xc2;
            }
        }
    }
    #pragma unroll
    for (int o = 0; o < OFFC; ++o) {
        g_off[((b*OFFC + o)*HH + yg)*WW + xg0     ] = acc[o][0];
        g_off[((b*OFFC + o)*HH + yg)*WW + xg0 + 32] = acc[o][1];
    }
}

// ---------------------------------------------------------------------------
// K2: deformable 3x3 conv 64->64 + BatchNorm + fused global-pool partial sums
// block = 2 rows x 64 px = 128 pixels, all 64 out channels; 256 threads,
// 4 adjacent pixels x 8 outputs per thread; grid (3, 96, 4); dynamic smem.
// Tap metadata recomputed in registers per tap (no smem) -> 49 KB, 4 CTAs/SM.
// ---------------------------------------------------------------------------
__global__ __launch_bounds__(256) void deform_bn_kernel(
        const float* __restrict__ x,
        const float* __restrict__ db,
        const float* __restrict__ gma,
        const float* __restrict__ bta,
        const float* __restrict__ mean,
        const float* __restrict__ var) {
    extern __shared__ __align__(16) float smem[];
    float* dw_s   = smem + DW_S_OFF;     // one tap [o][c]: 16 KB
    float* samp_s = smem + SAMP_S_OFF;   // [c][pixel 0..127], pitch 132

    const int tid = threadIdx.x;
    const int b   = blockIdx.z;
    const int y0  = blockIdx.y * 2;
    const int x0b = blockIdx.x * 64;
    const int pq  = tid & 31;        // pixel-quad index: pixels 4pq..4pq+3
    const int og  = tid >> 5;        // output-channel group 0..7
    const int ppg = tid & 127;       // gather pixel 0..127
    const int cg  = tid >> 7;        // gather channel parity 0..1

    const float* xb = x + (size_t)b*CC*HWX;

    // fixed gather-pixel coordinates for this thread
    const int grow = ppg >> 6, gcol = ppg & 63;
    const int yy = y0 + grow, xx = x0b + gcol;
    const float* offpix = g_off + (size_t)b*OFFC*HWX + yy*WW + xx;

    float acc[8][4];
    #pragma unroll
    for (int r = 0; r < 8; ++r) {
        float bv = db[og*8 + r];
        acc[r][0] = bv; acc[r][1] = bv; acc[r][2] = bv; acc[r][3] = bv;
    }

    #pragma unroll 1
    for (int kk = 0; kk < 9; ++kk) {
        const int i = kk/3, j = kk%3;
        // ---- per-tap bilinear metadata in registers ----
        float oy = offpix[(2*kk  )*HWX];
        float ox = offpix[(2*kk+1)*HWX];
        float py = (float)(yy + i - 1) + oy;
        float px = (float)(xx + j - 1) + ox;
        float fy = floorf(py), fx = floorf(px);
        int yq = (int)fy, xq = (int)fx;
        float wy = py - fy, wx = px - fx;
        float vy0 = ((unsigned)yq     < (unsigned)HH) ? 1.f : 0.f;
        float vy1 = ((unsigned)(yq+1) < (unsigned)HH) ? 1.f : 0.f;
        float vx0 = ((unsigned)xq     < (unsigned)WW) ? 1.f : 0.f;
        float vx1 = ((unsigned)(xq+1) < (unsigned)WW) ? 1.f : 0.f;
        float w00 = (1.f-wy)*(1.f-wx)*vy0*vx0;
        float w01 = (1.f-wy)*wx      *vy0*vx1;
        float w10 = wy*(1.f-wx)      *vy1*vx0;
        float w11 = wy*wx            *vy1*vx1;
        int yc0 = min(max(yq,   0), HH-1);
        int yc1 = min(max(yq+1, 0), HH-1);
        int xc0 = min(max(xq,   0), WW-1);
        int xc1 = min(max(xq+1, 0), WW-1);
        int o00 = yc0*WW + xc0, o01 = yc0*WW + xc1;
        int o10 = yc1*WW + xc0, o11 = yc1*WW + xc1;

        // ---- gather 64x128 samples (32 per thread, fixed pixel) ----
        {
            const float* xc = xb + cg*HWX;
            #pragma unroll
            for (int r = 0; r < 32; ++r) {
                float v = w00*xc[o00] + w01*xc[o01] + w10*xc[o10] + w11*xc[o11];
                samp_s[(2*r + cg)*132 + ppg] = v;
                xc += 2*HWX;
            }
        }
        // ---- stage this tap's weights (coalesced, pre-transposed) ----
        for (int t = tid; t < 1024; t += 256)
            ((float4*)dw_s)[t] = ((const float4*)g_dwT)[kk*1024 + t];
        __syncthreads();

        // ---- register-tiled GEMM: acc[o][p] += dw[o][c] * samp[c][p] ----
        const float4* dw4 = (const float4*)dw_s;
        #pragma unroll 4
        for (int c4 = 0; c4 < 16; ++c4) {
            float4 s0 = *(const float4*)&samp_s[(4*c4+0)*132 + 4*pq];
            float4 s1 = *(const float4*)&samp_s[(4*c4+1)*132 + 4*pq];
            float4 s2 = *(const float4*)&samp_s[(4*c4+2)*132 + 4*pq];
            float4 s3 = *(const float4*)&samp_s[(4*c4+3)*132 + 4*pq];
            #pragma unroll
            for (int r = 0; r < 8; ++r) {
                float4 w = dw4[(og*8 + r)*16 + c4];
                acc[r][0] += w.x*s0.x + w.y*s1.x + w.z*s2.x + w.w*s3.x;
                acc[r][1] += w.x*s0.y + w.y*s1.y + w.z*s2.y + w.w*s3.y;
                acc[r][2] += w.x*s0.z + w.y*s1.z + w.z*s2.z + w.w*s3.z;
                acc[r][3] += w.x*s0.w + w.y*s1.w + w.z*s2.w + w.w*s3.w;
            }
        }
        __syncthreads();
    }

    // epilogue: BN, store, fused pool partial sums
    const int p0 = 4*pq;
    const int row = p0 >> 6, col = p0 & 63;
    #pragma unroll
    for (int r = 0; r < 8; ++r) {
        int o = og*8 + r;
        float inv = rsqrtf(var[o] + 1e-5f);
        float sc = gma[o]*inv, mu = mean[o], bt = bta[o];
        float4 v;
        v.x = (acc[r][0] - mu)*sc + bt;
        v.y = (acc[r][1] - mu)*sc + bt;
        v.z = (acc[r][2] - mu)*sc + bt;
        v.w = (acc[r][3] - mu)*sc + bt;
        *(float4*)&g_h[((b*CC + o)*HH + y0 + row)*WW + x0b + col] = v;
        float s = (v.x + v.y) + (v.z + v.w);
        #pragma unroll
        for (int off = 16; off > 0; off >>= 1)
            s += __shfl_xor_sync(0xffffffffu, s, off);
        if (pq == 0) atomicAdd(&g_pool[b*CC + o], s);
    }
}

// ---------------------------------------------------------------------------
// K3: SE MLP (hid=4): one block (scales pooled sums by 1/HW)
// ---------------------------------------------------------------------------
__global__ __launch_bounds__(256) void ca_kernel(
        const float* __restrict__ w1, const float* __restrict__ b1,
        const float* __restrict__ w2, const float* __restrict__ b2) {
    __shared__ float t[BB*HID];
    const int tid = threadIdx.x;
    const int b = tid >> 6, c = tid & 63;
    if (c < HID) {
        float s = b1[c];
        for (int cc = 0; cc < CC; ++cc)
            s += w1[c*CC + cc] * (g_pool[b*CC + cc] * (1.f/(float)HWX));
        t[b*HID + c] = fmaxf(s, 0.f);
    }
    __syncthreads();
    float s = b2[c];
    #pragma unroll
    for (int h = 0; h < HID; ++h) s += w2[c*HID + h] * t[b*HID + h];
    g_cw[tid] = 1.f / (1.f + expf(-s));
}

// ---------------------------------------------------------------------------
// K4: spatial attention 7x7 conv -> sigmoid -> fused final output
// tile 64x8, 256 threads, 2 pixels/thread (x and x+32); grid (3, 24, 4)
// ---------------------------------------------------------------------------
__global__ __launch_bounds__(256) void sa_final_kernel(
        const float* __restrict__ sa_w, const float* __restrict__ sa_b,
        float* __restrict__ out) {
    __shared__ float ws[CC*49];
    __shared__ float xs[14*70];
    __shared__ float cws[CC];
    const int tid = threadIdx.x;
    const int bx = blockIdx.x, by = blockIdx.y, b = blockIdx.z;
    const int lx = tid & 31, ly = tid >> 5;
    const int xg0 = bx*64 + lx, yg = by*8 + ly;

    for (int t = tid; t < CC*49; t += 256) ws[t] = sa_w[t];
    if (tid < CC) cws[tid] = g_cw[b*CC + tid];

    float acc0 = sa_b[0], acc1 = sa_b[0];
    const float* hb = g_h + (size_t)b*CC*HWX;

    #pragma unroll 1
    for (int c = 0; c < CC; ++c) {
        __syncthreads();
        for (int t = tid; t < 14*70; t += 256) {
            int r = t / 70, q = t % 70;
            int gy = by*8 + r - 3, gx = bx*64 + q - 3;
            float v = 0.f;
            if (gy >= 0 && gy < HH && gx >= 0 && gx < WW)
                v = hb[c*HWX + gy*WW + gx];
            xs[t] = v;
        }
        __syncthreads();
        float s0 = 0.f, s1 = 0.f;
        #pragma unroll
        for (int dy = 0; dy < 7; ++dy) {
            #pragma unroll
            for (int dx = 0; dx < 7; ++dx) {
                float w = ws[c*49 + dy*7 + dx];
                s0 += xs[(ly+dy)*70 + lx + dx     ] * w;
                s1 += xs[(ly+dy)*70 + lx + 32 + dx] * w;
            }
        }
        acc0 += s0 * cws[c];
        acc1 += s1 * cws[c];
    }
    float sw0 = 1.f / (1.f + expf(-acc0));
    float sw1 = 1.f / (1.f + expf(-acc1));

    // fused finalize: out = h * cw * sw for all 64 channels of this tile
    const int base = yg*WW + xg0;
    #pragma unroll 4
    for (int c = 0; c < CC; ++c) {
        float cw = cws[c];
        float h0 = hb[c*HWX + base];
        float h1 = hb[c*HWX + base + 32];
        out[((size_t)(b*CC + c))*HWX + base     ] = h0*cw*sw0;
        out[((size_t)(b*CC + c))*HWX + base + 32] = h1*cw*sw1;
    }
}

// ---------------------------------------------------------------------------
extern "C" void kernel_launch(void* const* d_in, const int* in_sizes, int n_in,
                              void* d_out, int out_size) {
    const float* x      = (const float*)d_in[0];
    const float* off_w  = (const float*)d_in[1];
    const float* off_b  = (const float*)d_in[2];
    const float* dw     = (const float*)d_in[3];
    const float* db     = (const float*)d_in[4];
    const float* bn_g   = (const float*)d_in[5];
    const float* bn_b   = (const float*)d_in[6];
    const float* bn_m   = (const float*)d_in[7];
    const float* bn_v   = (const float*)d_in[8];
    const float* ca_w1  = (const float*)d_in[9];
    const float* ca_b1  = (const float*)d_in[10];
    const float* ca_w2  = (const float*)d_in[11];
    const float* ca_b2  = (const float*)d_in[12];
    const float* sa_w   = (const float*)d_in[13];
    const float* sa_b   = (const float*)d_in[14];
    float* out = (float*)d_out;

    cudaFuncSetAttribute(deform_bn_kernel,
                         cudaFuncAttributeMaxDynamicSharedMemorySize,
                         DEFORM_SMEM_BYTES);

    transpose_w_kernel<<<(9*CC*CC + CC*9*OFFC + 255)/256, 256>>>(dw, off_w);
    offset_conv_kernel<<<dim3(WW/64, HH/8, BB), 256>>>(x, off_b);
    deform_bn_kernel  <<<dim3(WW/64, HH/2, BB), 256, DEFORM_SMEM_BYTES>>>(
                          x, db, bn_g, bn_b, bn_m, bn_v);
    ca_kernel         <<<1, 256>>>(ca_w1, ca_b1, ca_w2, ca_b2);
    sa_final_kernel   <<<dim3(WW/64, HH/8, BB), 256>>>(sa_w, sa_b, out);
}